// round 1
// baseline (speedup 1.0000x reference)
#include <cuda_runtime.h>
#include <math.h>

#define NMAX 100000
#define FDIM 64

// Scratch (alloc-free: __device__ globals, zero-initialized at module load)
__device__ float g_t[NMAX * FDIM];    // h @ W   (per-layer linear output)
__device__ float g_acc[NMAX * FDIM];  // scatter-add accumulator
__device__ float g_h[NMAX * FDIM];    // layer activations

// ---------------------------------------------------------------------------
// Tiled GEMM: out[n,64] = in[n,K] @ W[K,64]
// Block: 64 rows x 64 cols, 256 threads, 4x4 micro-tile, K-chunks of 32.
// ---------------------------------------------------------------------------
template <int K>
__global__ __launch_bounds__(256)
void gemm_kernel(const float* __restrict__ in, const float* __restrict__ W,
                 float* __restrict__ out, int n) {
    constexpr int KT = 32;
    __shared__ float hT[KT][68];   // [k][m], padded to 68 (272B rows, 16B aligned)
    __shared__ float Ws[KT][64];   // [k][ncol]

    const int tid = threadIdx.x;
    const int m4  = tid & 15;      // row-group (4 rows each)
    const int n4  = tid >> 4;      // col-group (4 cols each)
    const int row0 = blockIdx.x * 64;

    float acc[4][4];
#pragma unroll
    for (int i = 0; i < 4; i++)
#pragma unroll
        for (int j = 0; j < 4; j++) acc[i][j] = 0.f;

    for (int k0 = 0; k0 < K; k0 += KT) {
        // Load input tile (64 rows x 32 k), store transposed into hT[k][m].
        // 512 float4 loads, 2 per thread.
#pragma unroll
        for (int i = tid; i < 64 * KT / 4; i += 256) {
            int r  = i >> 3;            // 8 float4 per row
            int kq = (i & 7) * 4;
            int grow = row0 + r;
            float4 v = make_float4(0.f, 0.f, 0.f, 0.f);
            if (grow < n) v = *(const float4*)&in[(long)grow * K + k0 + kq];
            hT[kq + 0][r] = v.x;
            hT[kq + 1][r] = v.y;
            hT[kq + 2][r] = v.z;
            hT[kq + 3][r] = v.w;
        }
        // Load W tile (32 x 64), row-major, 512 float4, 2 per thread.
#pragma unroll
        for (int i = tid; i < KT * 64 / 4; i += 256) {
            int kk = i >> 4;            // 16 float4 per row
            int cc = (i & 15) * 4;
            *(float4*)&Ws[kk][cc] = *(const float4*)&W[(long)(k0 + kk) * 64 + cc];
        }
        __syncthreads();

#pragma unroll
        for (int k = 0; k < KT; k++) {
            float4 a = *(const float4*)&hT[k][m4 * 4];
            float4 w = *(const float4*)&Ws[k][n4 * 4];
            float av[4] = {a.x, a.y, a.z, a.w};
            float wv[4] = {w.x, w.y, w.z, w.w};
#pragma unroll
            for (int i = 0; i < 4; i++)
#pragma unroll
                for (int j = 0; j < 4; j++)
                    acc[i][j] = fmaf(av[i], wv[j], acc[i][j]);
        }
        __syncthreads();
    }

#pragma unroll
    for (int i = 0; i < 4; i++) {
        int row = row0 + m4 * 4 + i;
        if (row < n) {
            float4 o = make_float4(acc[i][0], acc[i][1], acc[i][2], acc[i][3]);
            *(float4*)&out[(long)row * 64 + n4 * 4] = o;
        }
    }
}

// ---------------------------------------------------------------------------
// Scatter-add: acc[dst] += t[src] for each edge. One thread per (edge, float4).
// float4 atomicAdd (sm_90+) => 16 vector-REDs per edge instead of 64 scalars.
// ---------------------------------------------------------------------------
__global__ __launch_bounds__(256)
void scatter_kernel(const int* __restrict__ ei, int E,
                    const float* __restrict__ t, float* __restrict__ acc) {
    long tid = (long)blockIdx.x * blockDim.x + threadIdx.x;
    int e = (int)(tid >> 4);
    if (e >= E) return;
    int c = (int)(tid & 15) << 2;
    int src = ei[e];
    int dst = ei[E + e];
    float4 v = *(const float4*)&t[(long)src * 64 + c];
    atomicAdd((float4*)&acc[(long)dst * 64 + c], v);
}

// ---------------------------------------------------------------------------
// Fused: h = relu(acc + b); acc = 0   (re-zero for next layer / next replay)
// ---------------------------------------------------------------------------
__global__ __launch_bounds__(256)
void bias_relu_zero_kernel(float* __restrict__ acc, const float* __restrict__ b,
                           float* __restrict__ h, int total) {
    long i4 = ((long)blockIdx.x * blockDim.x + threadIdx.x) * 4;
    if (i4 >= total) return;
    float4 v = *(float4*)&acc[i4];
    int c = (int)(i4 & 63);
    float4 bb = *(const float4*)&b[c];
    v.x = fmaxf(v.x + bb.x, 0.f);
    v.y = fmaxf(v.y + bb.y, 0.f);
    v.z = fmaxf(v.z + bb.z, 0.f);
    v.w = fmaxf(v.w + bb.w, 0.f);
    *(float4*)&h[i4] = v;
    *(float4*)&acc[i4] = make_float4(0.f, 0.f, 0.f, 0.f);
}

// ---------------------------------------------------------------------------
// Fused final: out = sigmoid(acc + b); acc = 0
// ---------------------------------------------------------------------------
__global__ __launch_bounds__(256)
void bias_sigmoid_zero_kernel(float* __restrict__ acc, const float* __restrict__ b,
                              float* __restrict__ out, int total) {
    long i4 = ((long)blockIdx.x * blockDim.x + threadIdx.x) * 4;
    if (i4 >= total) return;
    float4 v = *(float4*)&acc[i4];
    int c = (int)(i4 & 63);
    float4 bb = *(const float4*)&b[c];
    v.x = 1.f / (1.f + __expf(-(v.x + bb.x)));
    v.y = 1.f / (1.f + __expf(-(v.y + bb.y)));
    v.z = 1.f / (1.f + __expf(-(v.z + bb.z)));
    v.w = 1.f / (1.f + __expf(-(v.w + bb.w)));
    *(float4*)&out[i4] = v;
    *(float4*)&acc[i4] = make_float4(0.f, 0.f, 0.f, 0.f);
}

__global__ __launch_bounds__(256)
void zero_kernel(float* __restrict__ p, int total) {
    long i4 = ((long)blockIdx.x * blockDim.x + threadIdx.x) * 4;
    if (i4 >= total) return;
    *(float4*)&p[i4] = make_float4(0.f, 0.f, 0.f, 0.f);
}

extern "C" void kernel_launch(void* const* d_in, const int* in_sizes, int n_in,
                              void* d_out, int out_size) {
    const float* x  = (const float*)d_in[0];
    const int*   ei = (const int*)d_in[1];
    const float* W1 = (const float*)d_in[2];
    const float* b1 = (const float*)d_in[3];
    const float* W2 = (const float*)d_in[4];
    const float* b2 = (const float*)d_in[5];
    const float* W3 = (const float*)d_in[6];
    const float* b3 = (const float*)d_in[7];
    float* out = (float*)d_out;

    const int N = in_sizes[0] / 128;
    const int E = in_sizes[1] / 2;
    const int total = N * 64;

    float *t, *acc, *h;
    cudaGetSymbolAddress((void**)&t,   g_t);
    cudaGetSymbolAddress((void**)&acc, g_acc);
    cudaGetSymbolAddress((void**)&h,   g_h);

    const int eb = (int)(((long)E * 16 + 255) / 256);       // scatter blocks
    const int fb = (total / 4 + 255) / 256;                  // elementwise blocks
    const int gb = (N + 63) / 64;                            // gemm blocks

    // Safety: ensure accumulator starts at zero (idempotent after first call)
    zero_kernel<<<fb, 256>>>(acc, total);

    // Layer 1: x[N,128] @ W1 -> t ; scatter ; relu(+b1) -> h ; acc=0
    gemm_kernel<128><<<gb, 256>>>(x, W1, t, N);
    scatter_kernel<<<eb, 256>>>(ei, E, t, acc);
    bias_relu_zero_kernel<<<fb, 256>>>(acc, b1, h, total);

    // Layer 2
    gemm_kernel<64><<<gb, 256>>>(h, W2, t, N);
    scatter_kernel<<<eb, 256>>>(ei, E, t, acc);
    bias_relu_zero_kernel<<<fb, 256>>>(acc, b2, h, total);

    // Layer 3
    gemm_kernel<64><<<gb, 256>>>(h, W3, t, N);
    scatter_kernel<<<eb, 256>>>(ei, E, t, acc);
    bias_sigmoid_zero_kernel<<<fb, 256>>>(acc, b3, out, total);
}

// round 2
// speedup vs baseline: 1.6109x; 1.6109x over previous
#include <cuda_runtime.h>
#include <math.h>

#define NMAX 100000
#define EMAX 2000000
#define NB_SCAN ((NMAX + 1023) / 1024)   // 98

// Scratch (alloc-free: __device__ globals)
__device__ float g_t[NMAX * 64];      // h @ W
__device__ float g_h[NMAX * 64];      // layer activations
__device__ int   g_deg[NMAX];
__device__ int   g_incl[NMAX];
__device__ int   g_rp[NMAX + 1];
__device__ int   g_cursor[NMAX];
__device__ int   g_bsum[128];
__device__ int   g_csr[EMAX];

// ---------------------------------------------------------------------------
// Tiled GEMM: out[n,64] = in[n,K] @ W[K,64]
// ---------------------------------------------------------------------------
template <int K>
__global__ __launch_bounds__(256)
void gemm_kernel(const float* __restrict__ in, const float* __restrict__ W,
                 float* __restrict__ out, int n) {
    constexpr int KT = 32;
    __shared__ float hT[KT][68];
    __shared__ float Ws[KT][64];

    const int tid = threadIdx.x;
    const int m4  = tid & 15;
    const int n4  = tid >> 4;
    const int row0 = blockIdx.x * 64;

    float acc[4][4];
#pragma unroll
    for (int i = 0; i < 4; i++)
#pragma unroll
        for (int j = 0; j < 4; j++) acc[i][j] = 0.f;

    for (int k0 = 0; k0 < K; k0 += KT) {
#pragma unroll
        for (int i = tid; i < 64 * KT / 4; i += 256) {
            int r  = i >> 3;
            int kq = (i & 7) * 4;
            int grow = row0 + r;
            float4 v = make_float4(0.f, 0.f, 0.f, 0.f);
            if (grow < n) v = *(const float4*)&in[(long)grow * K + k0 + kq];
            hT[kq + 0][r] = v.x;
            hT[kq + 1][r] = v.y;
            hT[kq + 2][r] = v.z;
            hT[kq + 3][r] = v.w;
        }
#pragma unroll
        for (int i = tid; i < KT * 64 / 4; i += 256) {
            int kk = i >> 4;
            int cc = (i & 15) * 4;
            *(float4*)&Ws[kk][cc] = *(const float4*)&W[(long)(k0 + kk) * 64 + cc];
        }
        __syncthreads();

#pragma unroll
        for (int k = 0; k < KT; k++) {
            float4 a = *(const float4*)&hT[k][m4 * 4];
            float4 w = *(const float4*)&Ws[k][n4 * 4];
            float av[4] = {a.x, a.y, a.z, a.w};
            float wv[4] = {w.x, w.y, w.z, w.w};
#pragma unroll
            for (int i = 0; i < 4; i++)
#pragma unroll
                for (int j = 0; j < 4; j++)
                    acc[i][j] = fmaf(av[i], wv[j], acc[i][j]);
        }
        __syncthreads();
    }

#pragma unroll
    for (int i = 0; i < 4; i++) {
        int row = row0 + m4 * 4 + i;
        if (row < n) {
            float4 o = make_float4(acc[i][0], acc[i][1], acc[i][2], acc[i][3]);
            *(float4*)&out[(long)row * 64 + n4 * 4] = o;
        }
    }
}

// ---------------------------------------------------------------------------
// CSR construction
// ---------------------------------------------------------------------------
__global__ void zero_deg_kernel(int* __restrict__ deg, int n) {
    int i = blockIdx.x * blockDim.x + threadIdx.x;
    if (i < n) deg[i] = 0;
}

__global__ void hist_kernel(const int* __restrict__ ei, int E, int* __restrict__ deg) {
    int e = blockIdx.x * blockDim.x + threadIdx.x;
    if (e < E) atomicAdd(&deg[ei[E + e]], 1);
}

// scan1: per-block (1024 elems) inclusive scan + block sums
__global__ __launch_bounds__(256)
void scan1_kernel(const int* __restrict__ deg, int n,
                  int* __restrict__ incl, int* __restrict__ bsum) {
    __shared__ int s[1024];
    const int base = blockIdx.x * 1024;
    const int t = threadIdx.x;
#pragma unroll
    for (int j = 0; j < 4; j++) {
        int idx = t + j * 256;
        s[idx] = (base + idx < n) ? deg[base + idx] : 0;
    }
    __syncthreads();
    for (int off = 1; off < 1024; off <<= 1) {
        int v[4];
#pragma unroll
        for (int j = 0; j < 4; j++) {
            int idx = t + j * 256;
            v[j] = (idx >= off) ? s[idx - off] : 0;
        }
        __syncthreads();
#pragma unroll
        for (int j = 0; j < 4; j++) s[t + j * 256] += v[j];
        __syncthreads();
    }
#pragma unroll
    for (int j = 0; j < 4; j++) {
        int idx = t + j * 256;
        if (base + idx < n) incl[base + idx] = s[idx];
    }
    if (t == 0) bsum[blockIdx.x] = s[1023];
}

// scan2: single-block inclusive scan of block sums (nb <= 128)
__global__ __launch_bounds__(128)
void scan2_kernel(int* __restrict__ bsum, int nb) {
    __shared__ int s[128];
    int t = threadIdx.x;
    s[t] = (t < nb) ? bsum[t] : 0;
    __syncthreads();
    for (int off = 1; off < 128; off <<= 1) {
        int v = (t >= off) ? s[t - off] : 0;
        __syncthreads();
        s[t] += v;
        __syncthreads();
    }
    if (t < nb) bsum[t] = s[t];
}

// scan3: exclusive row_ptr + cursor copy
__global__ void scan3_kernel(const int* __restrict__ incl, const int* __restrict__ deg,
                             const int* __restrict__ bsum, int n, int E,
                             int* __restrict__ rp, int* __restrict__ cursor) {
    int i = blockIdx.x * blockDim.x + threadIdx.x;
    if (i >= n) return;
    int b = i >> 10;
    int add = b ? bsum[b - 1] : 0;
    int excl = incl[i] - deg[i] + add;
    rp[i] = excl;
    cursor[i] = excl;
    if (i == n - 1) rp[n] = E;
}

__global__ void fill_kernel(const int* __restrict__ ei, int E,
                            int* __restrict__ cursor, int* __restrict__ csr) {
    int e = blockIdx.x * blockDim.x + threadIdx.x;
    if (e >= E) return;
    int src = ei[e];
    int dst = ei[E + e];
    int pos = atomicAdd(&cursor[dst], 1);
    csr[pos] = src;
}

// ---------------------------------------------------------------------------
// Gather-reduce + bias + activation. One warp per destination node.
// Each lane owns 2 consecutive feature columns (float2) -> 256B coalesced reads.
// ---------------------------------------------------------------------------
template <bool SIGMOID>
__global__ __launch_bounds__(256)
void gather_kernel(const int* __restrict__ rp, const int* __restrict__ csr,
                   const float* __restrict__ t, const float* __restrict__ bias,
                   float* __restrict__ out, int n) {
    int warp = (blockIdx.x * blockDim.x + threadIdx.x) >> 5;
    int lane = threadIdx.x & 31;
    if (warp >= n) return;

    int s0 = rp[warp];
    int s1 = rp[warp + 1];

    float ax = 0.f, ay = 0.f;
    int e = s0;
    // unroll-4 for memory-level parallelism
    for (; e + 3 < s1; e += 4) {
        int src0 = __ldg(&csr[e + 0]);
        int src1 = __ldg(&csr[e + 1]);
        int src2 = __ldg(&csr[e + 2]);
        int src3 = __ldg(&csr[e + 3]);
        float2 v0 = *(const float2*)&t[(long)src0 * 64 + lane * 2];
        float2 v1 = *(const float2*)&t[(long)src1 * 64 + lane * 2];
        float2 v2 = *(const float2*)&t[(long)src2 * 64 + lane * 2];
        float2 v3 = *(const float2*)&t[(long)src3 * 64 + lane * 2];
        ax += (v0.x + v1.x) + (v2.x + v3.x);
        ay += (v0.y + v1.y) + (v2.y + v3.y);
    }
    for (; e < s1; e++) {
        int src = __ldg(&csr[e]);
        float2 v = *(const float2*)&t[(long)src * 64 + lane * 2];
        ax += v.x;
        ay += v.y;
    }

    float2 bb = *(const float2*)&bias[lane * 2];
    ax += bb.x;
    ay += bb.y;
    float2 r;
    if (SIGMOID) {
        r.x = 1.f / (1.f + __expf(-ax));
        r.y = 1.f / (1.f + __expf(-ay));
    } else {
        r.x = fmaxf(ax, 0.f);
        r.y = fmaxf(ay, 0.f);
    }
    *(float2*)&out[(long)warp * 64 + lane * 2] = r;
}

extern "C" void kernel_launch(void* const* d_in, const int* in_sizes, int n_in,
                              void* d_out, int out_size) {
    const float* x  = (const float*)d_in[0];
    const int*   ei = (const int*)d_in[1];
    const float* W1 = (const float*)d_in[2];
    const float* b1 = (const float*)d_in[3];
    const float* W2 = (const float*)d_in[4];
    const float* b2 = (const float*)d_in[5];
    const float* W3 = (const float*)d_in[6];
    const float* b3 = (const float*)d_in[7];
    float* out = (float*)d_out;

    const int N = in_sizes[0] / 128;
    const int E = in_sizes[1] / 2;

    float *t, *h;
    int *deg, *incl, *rp, *cursor, *bsum, *csr;
    cudaGetSymbolAddress((void**)&t,      g_t);
    cudaGetSymbolAddress((void**)&h,      g_h);
    cudaGetSymbolAddress((void**)&deg,    g_deg);
    cudaGetSymbolAddress((void**)&incl,   g_incl);
    cudaGetSymbolAddress((void**)&rp,     g_rp);
    cudaGetSymbolAddress((void**)&cursor, g_cursor);
    cudaGetSymbolAddress((void**)&bsum,   g_bsum);
    cudaGetSymbolAddress((void**)&csr,    g_csr);

    const int nb_scan = (N + 1023) / 1024;
    const int nblk = (N + 255) / 256;
    const int eblk = (E + 255) / 256;
    const int gb   = (N + 63) / 64;
    const int wb   = (N + 7) / 8;        // gather: 8 warps/block, warp per node

    // --- CSR build (once per call, reused by all 3 layers) ---
    zero_deg_kernel<<<nblk, 256>>>(deg, N);
    hist_kernel<<<eblk, 256>>>(ei, E, deg);
    scan1_kernel<<<nb_scan, 256>>>(deg, N, incl, bsum);
    scan2_kernel<<<1, 128>>>(bsum, nb_scan);
    scan3_kernel<<<nblk, 256>>>(incl, deg, bsum, N, E, rp, cursor);
    fill_kernel<<<eblk, 256>>>(ei, E, cursor, csr);

    // --- Layer 1 ---
    gemm_kernel<128><<<gb, 256>>>(x, W1, t, N);
    gather_kernel<false><<<wb, 256>>>(rp, csr, t, b1, h, N);

    // --- Layer 2 ---
    gemm_kernel<64><<<gb, 256>>>(h, W2, t, N);
    gather_kernel<false><<<wb, 256>>>(rp, csr, t, b2, h, N);

    // --- Layer 3 ---
    gemm_kernel<64><<<gb, 256>>>(h, W3, t, N);
    gather_kernel<true><<<wb, 256>>>(rp, csr, t, b3, out, N);
}

// round 3
// speedup vs baseline: 1.8691x; 1.1603x over previous
#include <cuda_runtime.h>
#include <math.h>
#include <stdint.h>

#define NMAX 100000
#define EMAX 2000000

// Scratch (alloc-free: __device__ globals)
__device__ float g_t[NMAX * 64];      // h @ W
__device__ float g_h[NMAX * 64];      // layer activations
__device__ int   g_deg[NMAX];
__device__ int   g_incl[NMAX];
__device__ int   g_rp[NMAX + 1];
__device__ int   g_cursor[NMAX];
__device__ int   g_bsum[128];
__device__ int   g_csr[EMAX];

// ---------------------------------------------------------------------------
// Tensor-core GEMM: out[n,64] = in[n,K] @ W[K,64]  via mma.m16n8k8.tf32
// Block: 256 threads (8 warps), 128 rows/block, each warp 16 rows x 64 cols.
// W pre-arranged in fragment layout in smem (built once per block).
// A fragments loaded straight from global (L1-cached), no mainloop barriers.
// ---------------------------------------------------------------------------
__device__ __forceinline__ uint32_t f2tf32(float f) {
    uint32_t r;
    asm("cvt.rna.tf32.f32 %0, %1;" : "=r"(r) : "f"(f));
    return r;
}

template <int K>
__global__ __launch_bounds__(256)
void gemm_tc_kernel(const float* __restrict__ in, const float* __restrict__ W,
                    float* __restrict__ out, int n) {
    constexpr int KS = K / 8;                  // k-steps
    __shared__ uint32_t Wf[KS * 8 * 32 * 2];   // [ks][nb][lane][2]

    const int tid = threadIdx.x;

    // Build fragment-layout W once per block.
    // b0 wants W[ks*8 + (lane&3)][nb*8 + (lane>>2)], b1 = +4 on k.
    for (int idx = tid; idx < K * 64; idx += 256) {
        int k  = idx >> 6;
        int nn = idx & 63;
        int ks = k >> 3, kk = k & 7;
        int ch = kk >> 2, c = kk & 3;
        int nb = nn >> 3, ng = nn & 7;
        int lane = ng * 4 + c;
        Wf[(((ks * 8 + nb) * 32) + lane) * 2 + ch] = f2tf32(W[idx]);
    }
    __syncthreads();

    const int w    = tid >> 5;
    const int lane = tid & 31;
    const int grp  = lane >> 2;   // 0..7
    const int tig  = lane & 3;    // 0..3

    const int r0 = blockIdx.x * 128 + w * 16 + grp;
    const int r1 = r0 + 8;
    const bool v0 = r0 < n;
    const bool v1 = r1 < n;
    const float* p0 = in + (long)r0 * K + tig;
    const float* p1 = in + (long)r1 * K + tig;

    float acc[8][4];
#pragma unroll
    for (int nb = 0; nb < 8; nb++)
#pragma unroll
        for (int j = 0; j < 4; j++) acc[nb][j] = 0.f;

#pragma unroll
    for (int ks = 0; ks < KS; ks++) {
        // A fragment (16x8 tf32), direct from global
        float a0f = v0 ? __ldg(p0 + ks * 8)     : 0.f;
        float a1f = v1 ? __ldg(p1 + ks * 8)     : 0.f;
        float a2f = v0 ? __ldg(p0 + ks * 8 + 4) : 0.f;
        float a3f = v1 ? __ldg(p1 + ks * 8 + 4) : 0.f;
        uint32_t a0 = f2tf32(a0f), a1 = f2tf32(a1f);
        uint32_t a2 = f2tf32(a2f), a3 = f2tf32(a3f);

        const uint32_t* wbase = &Wf[(ks * 8) * 64 + lane * 2];
#pragma unroll
        for (int nb = 0; nb < 8; nb++) {
            uint2 bb = *(const uint2*)(wbase + nb * 64);
            asm volatile(
                "mma.sync.aligned.m16n8k8.row.col.f32.tf32.tf32.f32 "
                "{%0,%1,%2,%3}, {%4,%5,%6,%7}, {%8,%9}, {%0,%1,%2,%3};"
                : "+f"(acc[nb][0]), "+f"(acc[nb][1]),
                  "+f"(acc[nb][2]), "+f"(acc[nb][3])
                : "r"(a0), "r"(a1), "r"(a2), "r"(a3),
                  "r"(bb.x), "r"(bb.y));
        }
    }

    // Epilogue: c0,c1 -> (r0, nb*8 + tig*2), c2,c3 -> (r1, same cols)
#pragma unroll
    for (int nb = 0; nb < 8; nb++) {
        int col = nb * 8 + tig * 2;
        if (v0) *(float2*)&out[(long)r0 * 64 + col] = make_float2(acc[nb][0], acc[nb][1]);
        if (v1) *(float2*)&out[(long)r1 * 64 + col] = make_float2(acc[nb][2], acc[nb][3]);
    }
}

// ---------------------------------------------------------------------------
// CSR construction
// ---------------------------------------------------------------------------
__global__ void zero_deg_kernel(int* __restrict__ deg, int n) {
    int i = blockIdx.x * blockDim.x + threadIdx.x;
    if (i < n) deg[i] = 0;
}

__global__ void hist_kernel(const int* __restrict__ ei, int E, int* __restrict__ deg) {
    int e = blockIdx.x * blockDim.x + threadIdx.x;
    if (e < E) atomicAdd(&deg[ei[E + e]], 1);
}

__global__ __launch_bounds__(256)
void scan1_kernel(const int* __restrict__ deg, int n,
                  int* __restrict__ incl, int* __restrict__ bsum) {
    __shared__ int s[1024];
    const int base = blockIdx.x * 1024;
    const int t = threadIdx.x;
#pragma unroll
    for (int j = 0; j < 4; j++) {
        int idx = t + j * 256;
        s[idx] = (base + idx < n) ? deg[base + idx] : 0;
    }
    __syncthreads();
    for (int off = 1; off < 1024; off <<= 1) {
        int v[4];
#pragma unroll
        for (int j = 0; j < 4; j++) {
            int idx = t + j * 256;
            v[j] = (idx >= off) ? s[idx - off] : 0;
        }
        __syncthreads();
#pragma unroll
        for (int j = 0; j < 4; j++) s[t + j * 256] += v[j];
        __syncthreads();
    }
#pragma unroll
    for (int j = 0; j < 4; j++) {
        int idx = t + j * 256;
        if (base + idx < n) incl[base + idx] = s[idx];
    }
    if (t == 0) bsum[blockIdx.x] = s[1023];
}

__global__ __launch_bounds__(128)
void scan2_kernel(int* __restrict__ bsum, int nb) {
    __shared__ int s[128];
    int t = threadIdx.x;
    s[t] = (t < nb) ? bsum[t] : 0;
    __syncthreads();
    for (int off = 1; off < 128; off <<= 1) {
        int v = (t >= off) ? s[t - off] : 0;
        __syncthreads();
        s[t] += v;
        __syncthreads();
    }
    if (t < nb) bsum[t] = s[t];
}

__global__ void scan3_kernel(const int* __restrict__ incl, const int* __restrict__ deg,
                             const int* __restrict__ bsum, int n, int E,
                             int* __restrict__ rp, int* __restrict__ cursor) {
    int i = blockIdx.x * blockDim.x + threadIdx.x;
    if (i >= n) return;
    int b = i >> 10;
    int add = b ? bsum[b - 1] : 0;
    int excl = incl[i] - deg[i] + add;
    rp[i] = excl;
    cursor[i] = excl;
    if (i == n - 1) rp[n] = E;
}

__global__ void fill_kernel(const int* __restrict__ ei, int E,
                            int* __restrict__ cursor, int* __restrict__ csr) {
    int e = blockIdx.x * blockDim.x + threadIdx.x;
    if (e >= E) return;
    int src = ei[e];
    int dst = ei[E + e];
    int pos = atomicAdd(&cursor[dst], 1);
    csr[pos] = src;
}

// ---------------------------------------------------------------------------
// Gather-reduce + bias + activation. One warp per destination node.
// ---------------------------------------------------------------------------
template <bool SIGMOID>
__global__ __launch_bounds__(256)
void gather_kernel(const int* __restrict__ rp, const int* __restrict__ csr,
                   const float* __restrict__ t, const float* __restrict__ bias,
                   float* __restrict__ out, int n) {
    int warp = (blockIdx.x * blockDim.x + threadIdx.x) >> 5;
    int lane = threadIdx.x & 31;
    if (warp >= n) return;

    int s0 = rp[warp];
    int s1 = rp[warp + 1];

    float ax = 0.f, ay = 0.f;
    int e = s0;
    for (; e + 3 < s1; e += 4) {
        int src0 = __ldg(&csr[e + 0]);
        int src1 = __ldg(&csr[e + 1]);
        int src2 = __ldg(&csr[e + 2]);
        int src3 = __ldg(&csr[e + 3]);
        float2 v0 = *(const float2*)&t[(long)src0 * 64 + lane * 2];
        float2 v1 = *(const float2*)&t[(long)src1 * 64 + lane * 2];
        float2 v2 = *(const float2*)&t[(long)src2 * 64 + lane * 2];
        float2 v3 = *(const float2*)&t[(long)src3 * 64 + lane * 2];
        ax += (v0.x + v1.x) + (v2.x + v3.x);
        ay += (v0.y + v1.y) + (v2.y + v3.y);
    }
    for (; e < s1; e++) {
        int src = __ldg(&csr[e]);
        float2 v = *(const float2*)&t[(long)src * 64 + lane * 2];
        ax += v.x;
        ay += v.y;
    }

    float2 bb = *(const float2*)&bias[lane * 2];
    ax += bb.x;
    ay += bb.y;
    float2 r;
    if (SIGMOID) {
        r.x = 1.f / (1.f + __expf(-ax));
        r.y = 1.f / (1.f + __expf(-ay));
    } else {
        r.x = fmaxf(ax, 0.f);
        r.y = fmaxf(ay, 0.f);
    }
    *(float2*)&out[(long)warp * 64 + lane * 2] = r;
}

extern "C" void kernel_launch(void* const* d_in, const int* in_sizes, int n_in,
                              void* d_out, int out_size) {
    const float* x  = (const float*)d_in[0];
    const int*   ei = (const int*)d_in[1];
    const float* W1 = (const float*)d_in[2];
    const float* b1 = (const float*)d_in[3];
    const float* W2 = (const float*)d_in[4];
    const float* b2 = (const float*)d_in[5];
    const float* W3 = (const float*)d_in[6];
    const float* b3 = (const float*)d_in[7];
    float* out = (float*)d_out;

    const int N = in_sizes[0] / 128;
    const int E = in_sizes[1] / 2;

    float *t, *h;
    int *deg, *incl, *rp, *cursor, *bsum, *csr;
    cudaGetSymbolAddress((void**)&t,      g_t);
    cudaGetSymbolAddress((void**)&h,      g_h);
    cudaGetSymbolAddress((void**)&deg,    g_deg);
    cudaGetSymbolAddress((void**)&incl,   g_incl);
    cudaGetSymbolAddress((void**)&rp,     g_rp);
    cudaGetSymbolAddress((void**)&cursor, g_cursor);
    cudaGetSymbolAddress((void**)&bsum,   g_bsum);
    cudaGetSymbolAddress((void**)&csr,    g_csr);

    const int nb_scan = (N + 1023) / 1024;
    const int nblk = (N + 255) / 256;
    const int eblk = (E + 255) / 256;
    const int gb   = (N + 127) / 128;    // tensor gemm: 128 rows/block
    const int wb   = (N + 7) / 8;        // gather: 8 warps/block

    // --- CSR build (reused by all 3 layers) ---
    zero_deg_kernel<<<nblk, 256>>>(deg, N);
    hist_kernel<<<eblk, 256>>>(ei, E, deg);
    scan1_kernel<<<nb_scan, 256>>>(deg, N, incl, bsum);
    scan2_kernel<<<1, 128>>>(bsum, nb_scan);
    scan3_kernel<<<nblk, 256>>>(incl, deg, bsum, N, E, rp, cursor);
    fill_kernel<<<eblk, 256>>>(ei, E, cursor, csr);

    // --- Layer 1 ---
    gemm_tc_kernel<128><<<gb, 256>>>(x, W1, t, N);
    gather_kernel<false><<<wb, 256>>>(rp, csr, t, b1, h, N);

    // --- Layer 2 ---
    gemm_tc_kernel<64><<<gb, 256>>>(h, W2, t, N);
    gather_kernel<false><<<wb, 256>>>(rp, csr, t, b2, h, N);

    // --- Layer 3 ---
    gemm_tc_kernel<64><<<gb, 256>>>(h, W3, t, N);
    gather_kernel<true><<<wb, 256>>>(rp, csr, t, b3, out, N);
}